// round 1
// baseline (speedup 1.0000x reference)
#include <cuda_runtime.h>

// Problem geometry
#define NB   8
#define CC   256
#define HH   52
#define WW   52
#define FNO  512
#define HP   54            // padded H
#define WP   54            // padded W
#define OHW  (HH * WW)     // 2704 output pixels per image
#define MTOT (NB * OHW)    // 21632 GEMM rows
#define CSTR (HP * WP)     // 2916 floats per channel plane

// Scratch: quantized + zero-padded input, fp32. 8*256*54*54*4 B = ~23.9 MB.
__device__ float g_xpad[NB * CC * HP * WP];

// ---------------------------------------------------------------------------
// Kernel 1: quantize input (round-half-even, clip to [-128,127]) into padded
// buffer. Padding ring written as 0 every launch (deterministic).
// ---------------------------------------------------------------------------
__global__ void quant_pad_kernel(const float* __restrict__ in) {
    int idx = blockIdx.x * blockDim.x + threadIdx.x;
    const int total = NB * CC * HP * WP;
    if (idx >= total) return;
    int x  = idx % WP;
    int y  = (idx / WP) % HP;
    int nc = idx / CSTR;
    float v = 0.0f;
    if (x >= 1 && x < WP - 1 && y >= 1 && y < HP - 1) {
        float t = rintf(in[(nc * HH + (y - 1)) * WW + (x - 1)] * 20.0f);
        v = fminf(127.0f, fmaxf(-128.0f, t));
    }
    g_xpad[idx] = v;
}

// ---------------------------------------------------------------------------
// Kernel 2: implicit-GEMM conv. Block tile 128(M) x 128(F), 256 threads,
// 8x8 accumulators per thread. K loop: 9 taps x (256 channels / 8).
// A gathered from g_xpad (coalesced along ox), B = weight rows (float4).
// Epilogue fuses bias, 0.25 scale, rintf, clip; stores coalesced along ox.
// ---------------------------------------------------------------------------
__global__ __launch_bounds__(256, 2)
void conv_gemm_kernel(const float* __restrict__ weight,
                      const float* __restrict__ bias,
                      float* __restrict__ out) {
    __shared__ float As[8][128];   // [k][m-row]
    __shared__ float Bs[8][128];   // [k][f-col]

    const int tid = threadIdx.x;
    const int bm  = blockIdx.y * 128;   // M tile base (21632 / 128 = 169, exact)
    const int bn  = blockIdx.x * 128;   // F tile base (512 / 128 = 4, exact)

    // ---- A loader mapping: 256 threads load 128 rows x 8 k, 4 scalars each
    const int ar  = tid & 127;          // which m-row of the tile
    const int ajg = (tid >> 7) << 2;    // k-subgroup base: 0 or 4
    int am   = bm + ar;
    int an   = am / OHW;
    int arem = am - an * OHW;
    int aoy  = arem / WW;
    int aox  = arem - aoy * WW;
    // padded-buffer base for (n, c=0, y=aoy, x=aox); tap adds fh*WP + fw,
    // channel adds c*CSTR. (orig pixel (i,j) sits at padded (i+1,j+1); tap
    // fh-1 offset => padded coord aoy+fh exactly.)
    const int abase = (an * CC * HP + aoy) * WP + aox;

    // ---- B loader mapping: 8 k-rows x 128 cols via float4
    const int bj = tid >> 5;            // k row 0..7
    const int bl = (tid & 31) << 2;     // col within row

    // ---- compute mapping: tx -> M rows (coalesced epilogue), ty -> F cols
    const int tx4 = (tid & 15) << 2;
    const int ty4 = (tid >> 4) << 2;

    float acc[8][8];
#pragma unroll
    for (int i = 0; i < 8; ++i)
#pragma unroll
        for (int j = 0; j < 8; ++j) acc[i][j] = 0.0f;

#pragma unroll 1
    for (int tap = 0; tap < 9; ++tap) {
        const int fh = tap / 3, fw = tap - fh * 3;
        const float* aptr = g_xpad + abase + fh * WP + fw;   // + c*CSTR per ch
#pragma unroll 1
        for (int c0 = 0; c0 < CC; c0 += 8) {
            // stage gmem loads in registers (overlaps prior tile compute)
            float ra[4];
#pragma unroll
            for (int u = 0; u < 4; ++u)
                ra[u] = aptr[(c0 + ajg + u) * CSTR];
            float4 rb = *(const float4*)&weight[((c0 + bj) * 9 + tap) * FNO + bn + bl];

            __syncthreads();
#pragma unroll
            for (int u = 0; u < 4; ++u) As[ajg + u][ar] = ra[u];
            *(float4*)&Bs[bj][bl] = rb;
            __syncthreads();

#pragma unroll
            for (int k = 0; k < 8; ++k) {
                float a[8], b[8];
                float4 t;
                t = *(const float4*)&As[k][tx4];      a[0]=t.x; a[1]=t.y; a[2]=t.z; a[3]=t.w;
                t = *(const float4*)&As[k][64 + tx4]; a[4]=t.x; a[5]=t.y; a[6]=t.z; a[7]=t.w;
                t = *(const float4*)&Bs[k][ty4];      b[0]=t.x; b[1]=t.y; b[2]=t.z; b[3]=t.w;
                t = *(const float4*)&Bs[k][64 + ty4]; b[4]=t.x; b[5]=t.y; b[6]=t.z; b[7]=t.w;
#pragma unroll
                for (int i = 0; i < 8; ++i)
#pragma unroll
                    for (int j = 0; j < 8; ++j)
                        acc[i][j] += a[i] * b[j];
            }
        }
    }

    // ---- epilogue: out = clip(round(0.25*acc + 4*bias), -128, 127), NCHW
    float bv[8];
#pragma unroll
    for (int j = 0; j < 8; ++j) {
        int f = bn + ((j < 4) ? (ty4 + j) : (64 + ty4 + j - 4));
        bv[j] = bias[f] * 4.0f;
    }
#pragma unroll
    for (int i = 0; i < 8; ++i) {
        int row  = bm + ((i < 4) ? (tx4 + i) : (64 + tx4 + i - 4));
        int n    = row / OHW;
        int rem  = row - n * OHW;
        int oy   = rem / WW;
        int ox   = rem - oy * WW;
        int obase = (n * FNO) * OHW + oy * WW + ox;   // + f*OHW per column
#pragma unroll
        for (int j = 0; j < 8; ++j) {
            int f = bn + ((j < 4) ? (ty4 + j) : (64 + ty4 + j - 4));
            float v = rintf(acc[i][j] * 0.25f + bv[j]);
            v = fminf(127.0f, fmaxf(-128.0f, v));
            out[obase + f * OHW] = v;
        }
    }
}

// ---------------------------------------------------------------------------
// Harness entry. Inputs (metadata order): input_data f32, weight f32, bias f32.
// Output: float32 [8, 512, 52, 52].
// ---------------------------------------------------------------------------
extern "C" void kernel_launch(void* const* d_in, const int* in_sizes, int n_in,
                              void* d_out, int out_size) {
    const float* in_data = (const float*)d_in[0];
    const float* weight  = (const float*)d_in[1];
    const float* bias    = (const float*)d_in[2];
    float* out = (float*)d_out;

    const int total = NB * CC * HP * WP;
    quant_pad_kernel<<<(total + 255) / 256, 256>>>(in_data);

    dim3 grid(FNO / 128, MTOT / 128);   // (4, 169)
    conv_gemm_kernel<<<grid, 256>>>(weight, bias, out);
}

// round 4
// speedup vs baseline: 2.0458x; 2.0458x over previous
#include <cuda_runtime.h>
#include <cuda_fp16.h>
#include <cstdint>

// ---------------- geometry ----------------
#define NB    8
#define CC    256
#define HH    52
#define WW    52
#define FNO   512
#define HP    54
#define WP    54
#define ROWS_N (HP*WP)          // 2916 padded-raster rows per image
#define MGLOB  (NB*ROWS_N)      // 23328 GEMM rows
#define OHW    (HH*WW)          // 2704

// ---------------- GEMM tiling ----------------
#define BM 256
#define BN 128
#define BK 32                   // channels per stage
#define STAGES 4
#define ITERS  72               // 9 taps * (256/32)
#define A_SM   (BM*64)          // 16 KB  (256 rows x 32 halfs)
#define B_SM   (2*BN*64)        // 16 KB  (2 splits x 128 rows x 32 halfs)
#define STG_SM (A_SM + B_SM)    // 32 KB
#define SMEM_TOTAL (STAGES*STG_SM)   // 128 KB

// XOR swizzle: 16B chunk k (0..3) within 64B row r  -> conflict-free ldmatrix
#define SWZ(r,k) (((r)<<6) + ((((k) ^ (((r)>>1)&3))) << 4))

// ---------------- device scratch ----------------
__device__ __half g_xh[MGLOB * CC];          // ~11.9 MB padded NHWC quantized fp16
__device__ __half g_w2[2 * 9 * FNO * CC];    // ~4.7 MB [split][tap][f][c] fp16

// ---------------- asm helpers ----------------
__device__ __forceinline__ uint32_t smem_u32(const void* p) {
    uint32_t a;
    asm("{ .reg .u64 t; cvta.to.shared.u64 t, %1; cvt.u32.u64 %0, t; }" : "=r"(a) : "l"(p));
    return a;
}
__device__ __forceinline__ void cp16(uint32_t s, const void* g) {
    asm volatile("cp.async.cg.shared.global [%0], [%1], 16;" :: "r"(s), "l"(g));
}
__device__ __forceinline__ void ldsm4(uint32_t& r0, uint32_t& r1, uint32_t& r2, uint32_t& r3,
                                      uint32_t a) {
    asm volatile("ldmatrix.sync.aligned.m8n8.x4.shared.b16 {%0,%1,%2,%3}, [%4];"
                 : "=r"(r0), "=r"(r1), "=r"(r2), "=r"(r3) : "r"(a));
}
__device__ __forceinline__ void mma16816(float* d, const uint32_t* a, const uint32_t* b) {
    asm volatile("mma.sync.aligned.m16n8k16.row.col.f32.f16.f16.f32 "
                 "{%0,%1,%2,%3}, {%4,%5,%6,%7}, {%8,%9}, {%0,%1,%2,%3};"
                 : "+f"(d[0]), "+f"(d[1]), "+f"(d[2]), "+f"(d[3])
                 : "r"(a[0]), "r"(a[1]), "r"(a[2]), "r"(a[3]), "r"(b[0]), "r"(b[1]));
}

// ---------------- kernel 0: zero padded activation buffer ----------------
__global__ void zero_xh_kernel() {
    const int total = (MGLOB * CC) / 8;   // uint4 count
    uint4 z = {0, 0, 0, 0};
    for (int i = blockIdx.x * blockDim.x + threadIdx.x; i < total; i += gridDim.x * blockDim.x)
        reinterpret_cast<uint4*>(g_xh)[i] = z;
}

// ---------------- kernel 1: quantize + NCHW->NHWC transpose (interior) -------
__global__ void quant_kernel(const float* __restrict__ in) {
    __shared__ float tile[32][33];
    const int n = blockIdx.z, y = blockIdx.y;
    const int xt = blockIdx.x & 1, ct = blockIdx.x >> 1;
    const int tx = threadIdx.x, ty = threadIdx.y;

    int x = xt * 32 + tx, c = ct * 32 + ty;
    if (x < WW) {
        float v = in[((n * CC + c) * HH + y) * WW + x];
        v = rintf(v * 20.0f);
        tile[ty][tx] = fminf(127.0f, fmaxf(-128.0f, v));
    }
    __syncthreads();
    int x2 = xt * 32 + ty, c2 = ct * 32 + tx;
    if (x2 < WW)
        g_xh[((size_t)n * ROWS_N + (y + 1) * WP + (x2 + 1)) * CC + c2] =
            __float2half_rn(tile[tx][ty]);
}

// ---------------- kernel 2: weight 2-way fp16 split + transpose --------------
// in:  weight[(c*9+tap)*512 + f]  fp32
// out: g_w2[((sp*9+tap)*512 + f)*256 + c]  fp16
__global__ void wprep_kernel(const float* __restrict__ w) {
    __shared__ __half t0[32][33], t1[32][33];
    const int tap = blockIdx.z;
    const int tx = threadIdx.x, ty = threadIdx.y;
    const int c = blockIdx.y * 32 + ty;
    const int f = blockIdx.x * 32 + tx;

    float v = w[((size_t)c * 9 + tap) * FNO + f];
    __half h0 = __float2half_rn(v);
    float r1 = v - __half2float(h0);
    __half h1 = __float2half_rn(r1);
    t0[ty][tx] = h0; t1[ty][tx] = h1;
    __syncthreads();

    const int c2 = blockIdx.y * 32 + tx;
    const int f2 = blockIdx.x * 32 + ty;
    size_t base = ((size_t)tap * FNO + f2) * CC + c2;
    const size_t sstr = (size_t)9 * FNO * CC;
    g_w2[base]        = t0[tx][ty];
    g_w2[base + sstr] = t1[tx][ty];
}

// ---------------- kernel 3: mma.sync implicit-GEMM conv ----------------------
__global__ __launch_bounds__(256, 1)
void conv_mma_kernel(const float* __restrict__ bias, float* __restrict__ out) {
    extern __shared__ char smem[];
    const uint32_t sb = smem_u32(smem);
    const int tid  = threadIdx.x;
    const int lane = tid & 31, wid = tid >> 5;
    const int fbase = blockIdx.x * BN;
    const int mbase = blockIdx.y * BM;
    const int wm = (wid & 3) << 6;   // warp m-offset (64)
    const int wn = (wid >> 2) << 6;  // warp n-offset (64)

    float acc[4][8][4];
#pragma unroll
    for (int a = 0; a < 4; ++a)
#pragma unroll
        for (int b = 0; b < 8; ++b)
#pragma unroll
            for (int c = 0; c < 4; ++c) acc[a][b][c] = 0.0f;

    auto issue = [&](int it) {
        const int tap = it >> 3;
        const int c0  = (it & 7) << 5;
        const int taprow = (tap / 3) * WP + (tap % 3);
        const uint32_t sA = sb + (uint32_t)(it & (STAGES - 1)) * STG_SM;
        const uint32_t sB = sA + A_SM;
        // A: 1024 chunks (256 rows x 4), 4 per thread
#pragma unroll
        for (int j = 0; j < 4; ++j) {
            int cid = tid + (j << 8);
            int r = cid >> 2, k = cid & 3;
            int grow = mbase + r + taprow;
            if (grow > MGLOB - 1) grow = MGLOB - 1;
            cp16(sA + SWZ(r, k), g_xh + (size_t)grow * CC + c0 + (k << 3));
        }
        // B: 1024 chunks (2 splits x 128 rows x 4), 4 per thread
#pragma unroll
        for (int j = 0; j < 4; ++j) {
            int cid = tid + (j << 8);
            int sp = cid >> 9, rem = cid & 511;
            int fr = rem >> 2, k = rem & 3;
            cp16(sB + sp * 8192 + SWZ(fr, k),
                 g_w2 + ((size_t)(sp * 9 + tap) * FNO + fbase + fr) * CC + c0 + (k << 3));
        }
        asm volatile("cp.async.commit_group;" ::: "memory");
    };

    // prologue: stages 0..2
    issue(0); issue(1); issue(2);

#pragma unroll 1
    for (int i = 0; i < ITERS; ++i) {
        asm volatile("cp.async.wait_group %0;" :: "n"(STAGES - 2) : "memory");
        __syncthreads();

        int nx = i + STAGES - 1;
        if (nx < ITERS) issue(nx);
        else asm volatile("cp.async.commit_group;" ::: "memory");

        const uint32_t sA = sb + (uint32_t)(i & (STAGES - 1)) * STG_SM;
        const uint32_t sB = sA + A_SM;
#pragma unroll
        for (int k16 = 0; k16 < 2; ++k16) {
            uint32_t a[4][4];
#pragma unroll
            for (int mi = 0; mi < 4; ++mi) {
                int r  = wm + (mi << 4) + (lane & 15);
                int kc = (k16 << 1) + (lane >> 4);
                ldsm4(a[mi][0], a[mi][1], a[mi][2], a[mi][3], sA + SWZ(r, kc));
            }
#pragma unroll
            for (int sp = 0; sp < 2; ++sp) {
#pragma unroll
                for (int nj = 0; nj < 4; ++nj) {
                    int r  = wn + (nj << 4) + ((lane >> 4) << 3) + (lane & 7);
                    int kc = (k16 << 1) + ((lane >> 3) & 1);
                    uint32_t b[4];
                    ldsm4(b[0], b[1], b[2], b[3], sB + sp * 8192 + SWZ(r, kc));
#pragma unroll
                    for (int mi = 0; mi < 4; ++mi) {
                        mma16816(acc[mi][nj * 2],     a[mi], b);
                        mma16816(acc[mi][nj * 2 + 1], a[mi], b + 2);
                    }
                }
            }
        }
    }

    // ---------------- epilogue: clip(round(0.25*acc + 4*bias)) -> NCHW -------
    // FIX vs R3: f-column index must include the warp's N offset `wn`.
    float bv[8][2];
#pragma unroll
    for (int nj2 = 0; nj2 < 8; ++nj2)
#pragma unroll
        for (int e = 0; e < 2; ++e)
            bv[nj2][e] = bias[fbase + wn + nj2 * 8 + ((lane & 3) << 1) + e] * 4.0f;

#pragma unroll
    for (int mi = 0; mi < 4; ++mi) {
        int m0 = mbase + wm + (mi << 4) + (lane >> 2);
#pragma unroll
        for (int half = 0; half < 2; ++half) {
            int g = m0 + half * 8;
            int n_img = g / ROWS_N;
            int rr = g - n_img * ROWS_N;
            int y = rr / WP;
            int x = rr - y * WP;
            bool valid = (g < MGLOB) && (y < HH) && (x < WW);
            float* ob = valid ? (out + ((size_t)n_img * FNO) * OHW + y * WW + x) : out;
#pragma unroll
            for (int nj2 = 0; nj2 < 8; ++nj2) {
#pragma unroll
                for (int e = 0; e < 2; ++e) {
                    int f = fbase + wn + nj2 * 8 + ((lane & 3) << 1) + e;
                    float v = acc[mi][nj2][half * 2 + e] * 0.25f + bv[nj2][e];
                    v = rintf(v);
                    v = fminf(127.0f, fmaxf(-128.0f, v));
                    if (valid) ob[(size_t)f * OHW] = v;
                }
            }
        }
    }
}

// ---------------- host ----------------
extern "C" void kernel_launch(void* const* d_in, const int* in_sizes, int n_in,
                              void* d_out, int out_size) {
    const float* in_data = (const float*)d_in[0];
    const float* weight  = (const float*)d_in[1];
    const float* bias    = (const float*)d_in[2];
    float* out = (float*)d_out;

    cudaFuncSetAttribute(conv_mma_kernel, cudaFuncAttributeMaxDynamicSharedMemorySize,
                         SMEM_TOTAL);

    zero_xh_kernel<<<2916, 256>>>();
    {
        dim3 grid(16, HH, NB), blk(32, 32);
        quant_kernel<<<grid, blk>>>(in_data);
    }
    {
        dim3 grid(FNO / 32, CC / 32, 9), blk(32, 32);
        wprep_kernel<<<grid, blk>>>(weight);
    }
    {
        dim3 grid(FNO / BN, (MGLOB + BM - 1) / BM);   // (4, 92)
        conv_mma_kernel<<<grid, 256, SMEM_TOTAL>>>(bias, out);
    }
}

// round 5
// speedup vs baseline: 3.7851x; 1.8501x over previous
#include <cuda_runtime.h>
#include <cuda_fp16.h>
#include <cstdint>

// ---------------- geometry ----------------
#define NB    8
#define CC    256
#define HH    52
#define WW    52
#define FNO   512
#define HP    54
#define WP    54
#define ROWS_N (HP*WP)          // 2916 padded-raster rows per image
#define MGLOB  (NB*ROWS_N)      // 23328 GEMM rows
#define OHW    (HH*WW)          // 2704

// ---------------- GEMM tiling ----------------
#define BM 128
#define BN 128
#define BK 32                   // channels per stage
#define STAGES 4
#define ITERS  72               // 9 taps * (256/32)
#define A_SM   (BM*64)          // 8 KB  (128 rows x 32 halfs)
#define B_SM   (2*BN*64)        // 16 KB (2 splits x 128 rows x 32 halfs)
#define STG_SM (A_SM + B_SM)    // 24 KB
#define SMEM_TOTAL (STAGES*STG_SM)   // 96 KB -> 2 CTAs/SM
#define MTILES ((MGLOB + BM - 1) / BM)   // 183

// XOR swizzle: 16B chunk k (0..3) within 64B row r  -> conflict-free ldmatrix
#define SWZ(r,k) (((r)<<6) + ((((k) ^ (((r)>>1)&3))) << 4))

// ---------------- device scratch ----------------
__device__ __half g_xh[MGLOB * CC];          // ~11.9 MB padded NHWC quantized fp16
__device__ __half g_w2[2 * 9 * FNO * CC];    // ~4.7 MB [split][tap][f][c] fp16

// ---------------- asm helpers ----------------
__device__ __forceinline__ uint32_t smem_u32(const void* p) {
    uint32_t a;
    asm("{ .reg .u64 t; cvta.to.shared.u64 t, %1; cvt.u32.u64 %0, t; }" : "=r"(a) : "l"(p));
    return a;
}
__device__ __forceinline__ void cp16(uint32_t s, const void* g) {
    asm volatile("cp.async.cg.shared.global [%0], [%1], 16;" :: "r"(s), "l"(g));
}
__device__ __forceinline__ void ldsm4(uint32_t& r0, uint32_t& r1, uint32_t& r2, uint32_t& r3,
                                      uint32_t a) {
    asm volatile("ldmatrix.sync.aligned.m8n8.x4.shared.b16 {%0,%1,%2,%3}, [%4];"
                 : "=r"(r0), "=r"(r1), "=r"(r2), "=r"(r3) : "r"(a));
}
__device__ __forceinline__ void mma16816(float* d, const uint32_t* a, const uint32_t* b) {
    asm volatile("mma.sync.aligned.m16n8k16.row.col.f32.f16.f16.f32 "
                 "{%0,%1,%2,%3}, {%4,%5,%6,%7}, {%8,%9}, {%0,%1,%2,%3};"
                 : "+f"(d[0]), "+f"(d[1]), "+f"(d[2]), "+f"(d[3])
                 : "r"(a[0]), "r"(a[1]), "r"(a[2]), "r"(a[3]), "r"(b[0]), "r"(b[1]));
}

// ---------------- kernel 0: zero padded activation buffer ----------------
__global__ void zero_xh_kernel() {
    const int total = (MGLOB * CC) / 8;   // uint4 count
    uint4 z = {0, 0, 0, 0};
    for (int i = blockIdx.x * blockDim.x + threadIdx.x; i < total; i += gridDim.x * blockDim.x)
        reinterpret_cast<uint4*>(g_xh)[i] = z;
}

// ---------------- kernel 1: quantize + NCHW->NHWC transpose (interior) -------
__global__ void quant_kernel(const float* __restrict__ in) {
    __shared__ float tile[32][33];
    const int n = blockIdx.z, y = blockIdx.y;
    const int xt = blockIdx.x & 1, ct = blockIdx.x >> 1;
    const int tx = threadIdx.x, ty = threadIdx.y;

    int x = xt * 32 + tx, c = ct * 32 + ty;
    if (x < WW) {
        float v = in[((n * CC + c) * HH + y) * WW + x];
        v = rintf(v * 20.0f);
        tile[ty][tx] = fminf(127.0f, fmaxf(-128.0f, v));
    }
    __syncthreads();
    int x2 = xt * 32 + ty, c2 = ct * 32 + tx;
    if (x2 < WW)
        g_xh[((size_t)n * ROWS_N + (y + 1) * WP + (x2 + 1)) * CC + c2] =
            __float2half_rn(tile[tx][ty]);
}

// ---------------- kernel 2: weight 2-way fp16 split + transpose --------------
// in:  weight[(c*9+tap)*512 + f]  fp32
// out: g_w2[((sp*9+tap)*512 + f)*256 + c]  fp16
__global__ void wprep_kernel(const float* __restrict__ w) {
    __shared__ __half t0[32][33], t1[32][33];
    const int tap = blockIdx.z;
    const int tx = threadIdx.x, ty = threadIdx.y;
    const int c = blockIdx.y * 32 + ty;
    const int f = blockIdx.x * 32 + tx;

    float v = w[((size_t)c * 9 + tap) * FNO + f];
    __half h0 = __float2half_rn(v);
    float r1 = v - __half2float(h0);
    __half h1 = __float2half_rn(r1);
    t0[ty][tx] = h0; t1[ty][tx] = h1;
    __syncthreads();

    const int c2 = blockIdx.y * 32 + tx;
    const int f2 = blockIdx.x * 32 + ty;
    size_t base = ((size_t)tap * FNO + f2) * CC + c2;
    const size_t sstr = (size_t)9 * FNO * CC;
    g_w2[base]        = t0[tx][ty];
    g_w2[base + sstr] = t1[tx][ty];
}

// ---------------- kernel 3: mma.sync implicit-GEMM conv ----------------------
// 128 threads (4 warps, 2x2 grid of 64x64 warp tiles), 2 CTAs/SM.
__global__ __launch_bounds__(128, 2)
void conv_mma_kernel(const float* __restrict__ bias, float* __restrict__ out) {
    extern __shared__ char smem[];
    const uint32_t sb = smem_u32(smem);
    const int tid  = threadIdx.x;
    const int lane = tid & 31, wid = tid >> 5;
    const int fbase = blockIdx.x * BN;
    const int mbase = blockIdx.y * BM;
    const int wm = (wid & 1) << 6;   // warp m-offset (0/64)
    const int wn = (wid >> 1) << 6;  // warp n-offset (0/64)

    float acc[4][8][4];
#pragma unroll
    for (int a = 0; a < 4; ++a)
#pragma unroll
        for (int b = 0; b < 8; ++b)
#pragma unroll
            for (int c = 0; c < 4; ++c) acc[a][b][c] = 0.0f;

    auto issue = [&](int it) {
        const int tap = it >> 3;
        const int c0  = (it & 7) << 5;
        const int taprow = (tap / 3) * WP + (tap % 3);
        const uint32_t sA = sb + (uint32_t)(it & (STAGES - 1)) * STG_SM;
        const uint32_t sB = sA + A_SM;
        // A: 512 chunks (128 rows x 4), 4 per thread
#pragma unroll
        for (int j = 0; j < 4; ++j) {
            int cid = tid + (j << 7);
            int r = cid >> 2, k = cid & 3;
            int grow = mbase + r + taprow;
            if (grow > MGLOB - 1) grow = MGLOB - 1;
            cp16(sA + SWZ(r, k), g_xh + (size_t)grow * CC + c0 + (k << 3));
        }
        // B: 1024 chunks (2 splits x 128 rows x 4), 8 per thread
#pragma unroll
        for (int j = 0; j < 8; ++j) {
            int cid = tid + (j << 7);
            int sp = cid >> 9, rem = cid & 511;
            int fr = rem >> 2, k = rem & 3;
            cp16(sB + sp * 8192 + SWZ(fr, k),
                 g_w2 + ((size_t)(sp * 9 + tap) * FNO + fbase + fr) * CC + c0 + (k << 3));
        }
        asm volatile("cp.async.commit_group;" ::: "memory");
    };

    // prologue: stages 0..2
    issue(0); issue(1); issue(2);

#pragma unroll 1
    for (int i = 0; i < ITERS; ++i) {
        asm volatile("cp.async.wait_group %0;" :: "n"(STAGES - 2) : "memory");
        __syncthreads();

        int nx = i + STAGES - 1;
        if (nx < ITERS) issue(nx);
        else asm volatile("cp.async.commit_group;" ::: "memory");

        const uint32_t sA = sb + (uint32_t)(i & (STAGES - 1)) * STG_SM;
        const uint32_t sB = sA + A_SM;
#pragma unroll
        for (int k16 = 0; k16 < 2; ++k16) {
            uint32_t a[4][4];
#pragma unroll
            for (int mi = 0; mi < 4; ++mi) {
                int r  = wm + (mi << 4) + (lane & 15);
                int kc = (k16 << 1) + (lane >> 4);
                ldsm4(a[mi][0], a[mi][1], a[mi][2], a[mi][3], sA + SWZ(r, kc));
            }
#pragma unroll
            for (int sp = 0; sp < 2; ++sp) {
#pragma unroll
                for (int nj = 0; nj < 4; ++nj) {
                    int r  = wn + (nj << 4) + ((lane >> 4) << 3) + (lane & 7);
                    int kc = (k16 << 1) + ((lane >> 3) & 1);
                    uint32_t b[4];
                    ldsm4(b[0], b[1], b[2], b[3], sB + sp * 8192 + SWZ(r, kc));
#pragma unroll
                    for (int mi = 0; mi < 4; ++mi) {
                        mma16816(acc[mi][nj * 2],     a[mi], b);
                        mma16816(acc[mi][nj * 2 + 1], a[mi], b + 2);
                    }
                }
            }
        }
    }

    // ---------------- epilogue: clip(round(0.25*acc + 4*bias)) -> NCHW -------
    float bv[8][2];
#pragma unroll
    for (int nj2 = 0; nj2 < 8; ++nj2)
#pragma unroll
        for (int e = 0; e < 2; ++e)
            bv[nj2][e] = bias[fbase + wn + nj2 * 8 + ((lane & 3) << 1) + e] * 4.0f;

#pragma unroll
    for (int mi = 0; mi < 4; ++mi) {
        int m0 = mbase + wm + (mi << 4) + (lane >> 2);
#pragma unroll
        for (int half = 0; half < 2; ++half) {
            int g = m0 + half * 8;
            int n_img = g / ROWS_N;
            int rr = g - n_img * ROWS_N;
            int y = rr / WP;
            int x = rr - y * WP;
            bool valid = (g < MGLOB) && (y < HH) && (x < WW);
            float* ob = valid ? (out + ((size_t)n_img * FNO) * OHW + y * WW + x) : out;
#pragma unroll
            for (int nj2 = 0; nj2 < 8; ++nj2) {
#pragma unroll
                for (int e = 0; e < 2; ++e) {
                    int f = fbase + wn + nj2 * 8 + ((lane & 3) << 1) + e;
                    float v = acc[mi][nj2][half * 2 + e] * 0.25f + bv[nj2][e];
                    v = rintf(v);
                    v = fminf(127.0f, fmaxf(-128.0f, v));
                    if (valid) ob[(size_t)f * OHW] = v;
                }
            }
        }
    }
}

// ---------------- host ----------------
extern "C" void kernel_launch(void* const* d_in, const int* in_sizes, int n_in,
                              void* d_out, int out_size) {
    const float* in_data = (const float*)d_in[0];
    const float* weight  = (const float*)d_in[1];
    const float* bias    = (const float*)d_in[2];
    float* out = (float*)d_out;

    cudaFuncSetAttribute(conv_mma_kernel, cudaFuncAttributeMaxDynamicSharedMemorySize,
                         SMEM_TOTAL);

    zero_xh_kernel<<<2916, 256>>>();
    {
        dim3 grid(16, HH, NB), blk(32, 32);
        quant_kernel<<<grid, blk>>>(in_data);
    }
    {
        dim3 grid(FNO / 32, CC / 32, 9), blk(32, 32);
        wprep_kernel<<<grid, blk>>>(weight);
    }
    {
        dim3 grid(FNO / BN, MTILES);   // (4, 183)
        conv_mma_kernel<<<grid, 128, SMEM_TOTAL>>>(bias, out);
    }
}

// round 6
// speedup vs baseline: 3.7978x; 1.0034x over previous
#include <cuda_runtime.h>
#include <cuda_fp16.h>
#include <cstdint>

// ---------------- geometry ----------------
#define NB    8
#define CC    256
#define HH    52
#define WW    52
#define FNO   512
#define HP    54
#define WP    54
#define ROWS_N (HP*WP)          // 2916 padded-raster rows per image
#define MGLOB  (NB*ROWS_N)      // 23328 GEMM rows
#define OHW    (HH*WW)          // 2704

// ---------------- GEMM tiling ----------------
#define BM 128
#define BN 128
#define BK 32                   // channels per stage
#define STAGES 4
#define ITERS  72               // 9 taps * (256/32)
#define A_SM   (BM*64)          // 8 KB
#define B_SM   (2*BN*64)        // 16 KB (2 splits)
#define STG_SM (A_SM + B_SM)    // 24 KB
#define SMEM_TOTAL (STAGES*STG_SM)   // 96 KB -> 2 CTAs/SM (192 KB)
#define MTILES ((MGLOB + BM - 1) / BM)   // 183

// XOR swizzle: 16B chunk k (0..3) within 64B row r  -> conflict-free ldmatrix
#define SWZ(r,k) (((r)<<6) + ((((k) ^ (((r)>>1)&3))) << 4))

// ---------------- device scratch ----------------
__device__ __half g_xh[MGLOB * CC];          // ~11.9 MB padded NHWC quantized fp16
__device__ __half g_w2[2 * 9 * FNO * CC];    // ~4.7 MB [split][tap][f][c] fp16

// ---------------- asm helpers ----------------
__device__ __forceinline__ uint32_t smem_u32(const void* p) {
    uint32_t a;
    asm("{ .reg .u64 t; cvta.to.shared.u64 t, %1; cvt.u32.u64 %0, t; }" : "=r"(a) : "l"(p));
    return a;
}
__device__ __forceinline__ void cp16(uint32_t s, const void* g) {
    asm volatile("cp.async.cg.shared.global [%0], [%1], 16;" :: "r"(s), "l"(g));
}
__device__ __forceinline__ void ldsm4(uint32_t& r0, uint32_t& r1, uint32_t& r2, uint32_t& r3,
                                      uint32_t a) {
    asm volatile("ldmatrix.sync.aligned.m8n8.x4.shared.b16 {%0,%1,%2,%3}, [%4];"
                 : "=r"(r0), "=r"(r1), "=r"(r2), "=r"(r3) : "r"(a));
}
__device__ __forceinline__ void mma16816(float* d, const uint32_t* a, const uint32_t* b) {
    asm volatile("mma.sync.aligned.m16n8k16.row.col.f32.f16.f16.f32 "
                 "{%0,%1,%2,%3}, {%4,%5,%6,%7}, {%8,%9}, {%0,%1,%2,%3};"
                 : "+f"(d[0]), "+f"(d[1]), "+f"(d[2]), "+f"(d[3])
                 : "r"(a[0]), "r"(a[1]), "r"(a[2]), "r"(a[3]), "r"(b[0]), "r"(b[1]));
}

// ---------------- kernel 0: zero only the padding halo ----------------
// Halo pixels per image: y in {0,53} (108) plus x in {0,53}, y in 1..52 (104) = 212.
__global__ void zero_halo_kernel() {
    // one uint4 (8 halfs) per thread: 8 images * 212 pixels * 32 vec = 54272 threads
    int idx = blockIdx.x * blockDim.x + threadIdx.x;
    const int total = NB * 212 * (CC / 8);
    if (idx >= total) return;
    int v = idx & 31;            // vec index within pixel (CC/8 = 32)
    int h = (idx >> 5) % 212;    // halo pixel index
    int n = idx / (212 * 32);
    int y, x;
    if (h < 54)       { y = 0;  x = h; }
    else if (h < 108) { y = 53; x = h - 54; }
    else { int r = h - 108; y = 1 + (r >> 1); x = (r & 1) ? 53 : 0; }
    uint4 z = {0, 0, 0, 0};
    reinterpret_cast<uint4*>(g_xh + ((size_t)n * ROWS_N + y * WP + x) * CC)[v] = z;
}

// ---------------- kernel 1: quantize + NCHW->NHWC transpose (interior) -------
__global__ void quant_kernel(const float* __restrict__ in) {
    __shared__ float tile[32][33];
    const int n = blockIdx.z, y = blockIdx.y;
    const int xt = blockIdx.x & 1, ct = blockIdx.x >> 1;
    const int tx = threadIdx.x, ty = threadIdx.y;

    int x = xt * 32 + tx, c = ct * 32 + ty;
    if (x < WW) {
        float v = in[((n * CC + c) * HH + y) * WW + x];
        v = rintf(v * 20.0f);
        tile[ty][tx] = fminf(127.0f, fmaxf(-128.0f, v));
    }
    __syncthreads();
    int x2 = xt * 32 + ty, c2 = ct * 32 + tx;
    if (x2 < WW)
        g_xh[((size_t)n * ROWS_N + (y + 1) * WP + (x2 + 1)) * CC + c2] =
            __float2half_rn(tile[tx][ty]);
}

// ---------------- kernel 2: weight 2-way fp16 split + transpose --------------
__global__ void wprep_kernel(const float* __restrict__ w) {
    __shared__ __half t0[32][33], t1[32][33];
    const int tap = blockIdx.z;
    const int tx = threadIdx.x, ty = threadIdx.y;
    const int c = blockIdx.y * 32 + ty;
    const int f = blockIdx.x * 32 + tx;

    float v = w[((size_t)c * 9 + tap) * FNO + f];
    __half h0 = __float2half_rn(v);
    float r1 = v - __half2float(h0);
    __half h1 = __float2half_rn(r1);
    t0[ty][tx] = h0; t1[ty][tx] = h1;
    __syncthreads();

    const int c2 = blockIdx.y * 32 + tx;
    const int f2 = blockIdx.x * 32 + ty;
    size_t base = ((size_t)tap * FNO + f2) * CC + c2;
    const size_t sstr = (size_t)9 * FNO * CC;
    g_w2[base]        = t0[tx][ty];
    g_w2[base + sstr] = t1[tx][ty];
}

// ---------------- kernel 3: mma.sync implicit-GEMM conv ----------------------
// 256 threads (8 warps, 2m x 4n grid of 64x32 warp tiles), 2 CTAs/SM.
__global__ __launch_bounds__(256, 2)
void conv_mma_kernel(const float* __restrict__ bias, float* __restrict__ out) {
    extern __shared__ char smem[];
    const uint32_t sb = smem_u32(smem);
    const int tid  = threadIdx.x;
    const int lane = tid & 31, wid = tid >> 5;
    const int fbase = blockIdx.x * BN;
    const int mbase = blockIdx.y * BM;
    const int wm = (wid & 1) << 6;   // warp m-offset (0/64)
    const int wn = (wid >> 1) << 5;  // warp n-offset (0/32/64/96)

    float acc[4][4][4];
#pragma unroll
    for (int a = 0; a < 4; ++a)
#pragma unroll
        for (int b = 0; b < 4; ++b)
#pragma unroll
            for (int c = 0; c < 4; ++c) acc[a][b][c] = 0.0f;

    auto issue = [&](int it) {
        const int tap = it >> 3;
        const int c0  = (it & 7) << 5;
        const int taprow = (tap / 3) * WP + (tap % 3);
        const uint32_t sA = sb + (uint32_t)(it & (STAGES - 1)) * STG_SM;
        const uint32_t sB = sA + A_SM;
        // A: 512 chunks (128 rows x 4), 2 per thread
#pragma unroll
        for (int j = 0; j < 2; ++j) {
            int cid = tid + (j << 8);
            int r = cid >> 2, k = cid & 3;
            int grow = mbase + r + taprow;
            if (grow > MGLOB - 1) grow = MGLOB - 1;
            cp16(sA + SWZ(r, k), g_xh + (size_t)grow * CC + c0 + (k << 3));
        }
        // B: 1024 chunks (2 splits x 128 rows x 4), 4 per thread
#pragma unroll
        for (int j = 0; j < 4; ++j) {
            int cid = tid + (j << 8);
            int sp = cid >> 9, rem = cid & 511;
            int fr = rem >> 2, k = rem & 3;
            cp16(sB + sp * 8192 + SWZ(fr, k),
                 g_w2 + ((size_t)(sp * 9 + tap) * FNO + fbase + fr) * CC + c0 + (k << 3));
        }
        asm volatile("cp.async.commit_group;" ::: "memory");
    };

    // prologue: stages 0..2
    issue(0); issue(1); issue(2);

#pragma unroll 1
    for (int i = 0; i < ITERS; ++i) {
        asm volatile("cp.async.wait_group %0;" :: "n"(STAGES - 2) : "memory");
        __syncthreads();

        int nx = i + STAGES - 1;
        if (nx < ITERS) issue(nx);
        else asm volatile("cp.async.commit_group;" ::: "memory");

        const uint32_t sA = sb + (uint32_t)(i & (STAGES - 1)) * STG_SM;
        const uint32_t sB = sA + A_SM;
#pragma unroll
        for (int k16 = 0; k16 < 2; ++k16) {
            uint32_t a[4][4];
#pragma unroll
            for (int mi = 0; mi < 4; ++mi) {
                int r  = wm + (mi << 4) + (lane & 15);
                int kc = (k16 << 1) + (lane >> 4);
                ldsm4(a[mi][0], a[mi][1], a[mi][2], a[mi][3], sA + SWZ(r, kc));
            }
#pragma unroll
            for (int sp = 0; sp < 2; ++sp) {
#pragma unroll
                for (int nj = 0; nj < 2; ++nj) {
                    int r  = wn + (nj << 4) + ((lane >> 4) << 3) + (lane & 7);
                    int kc = (k16 << 1) + ((lane >> 3) & 1);
                    uint32_t b[4];
                    ldsm4(b[0], b[1], b[2], b[3], sB + sp * 8192 + SWZ(r, kc));
#pragma unroll
                    for (int mi = 0; mi < 4; ++mi) {
                        mma16816(acc[mi][nj * 2],     a[mi], b);
                        mma16816(acc[mi][nj * 2 + 1], a[mi], b + 2);
                    }
                }
            }
        }
    }

    // ---------------- epilogue: clip(round(0.25*acc + 4*bias)) -> NCHW -------
    float bv[4][2];
#pragma unroll
    for (int nj2 = 0; nj2 < 4; ++nj2)
#pragma unroll
        for (int e = 0; e < 2; ++e)
            bv[nj2][e] = bias[fbase + wn + nj2 * 8 + ((lane & 3) << 1) + e] * 4.0f;

#pragma unroll
    for (int mi = 0; mi < 4; ++mi) {
        int m0 = mbase + wm + (mi << 4) + (lane >> 2);
#pragma unroll
        for (int half = 0; half < 2; ++half) {
            int g = m0 + half * 8;
            int n_img = g / ROWS_N;
            int rr = g - n_img * ROWS_N;
            int y = rr / WP;
            int x = rr - y * WP;
            bool valid = (g < MGLOB) && (y < HH) && (x < WW);
            float* ob = valid ? (out + ((size_t)n_img * FNO) * OHW + y * WW + x) : out;
#pragma unroll
            for (int nj2 = 0; nj2 < 4; ++nj2) {
#pragma unroll
                for (int e = 0; e < 2; ++e) {
                    int f = fbase + wn + nj2 * 8 + ((lane & 3) << 1) + e;
                    float v = acc[mi][nj2][half * 2 + e] * 0.25f + bv[nj2][e];
                    v = rintf(v);
                    v = fminf(127.0f, fmaxf(-128.0f, v));
                    if (valid) ob[(size_t)f * OHW] = v;
                }
            }
        }
    }
}

// ---------------- host ----------------
extern "C" void kernel_launch(void* const* d_in, const int* in_sizes, int n_in,
                              void* d_out, int out_size) {
    const float* in_data = (const float*)d_in[0];
    const float* weight  = (const float*)d_in[1];
    const float* bias    = (const float*)d_in[2];
    float* out = (float*)d_out;

    cudaFuncSetAttribute(conv_mma_kernel, cudaFuncAttributeMaxDynamicSharedMemorySize,
                         SMEM_TOTAL);

    {
        const int total = NB * 212 * (CC / 8);
        zero_halo_kernel<<<(total + 255) / 256, 256>>>();
    }
    {
        dim3 grid(16, HH, NB), blk(32, 32);
        quant_kernel<<<grid, blk>>>(in_data);
    }
    {
        dim3 grid(FNO / 32, CC / 32, 9), blk(32, 32);
        wprep_kernel<<<grid, blk>>>(weight);
    }
    {
        dim3 grid(FNO / BN, MTILES);   // (4, 183)
        conv_mma_kernel<<<grid, 256, SMEM_TOTAL>>>(bias, out);
    }
}